// round 11
// baseline (speedup 1.0000x reference)
#include <cuda_runtime.h>
#include <cuda_fp16.h>
#include <math.h>
#include <stdint.h>

#define L_ 2
#define F_ 128
#define O_ 128
#define N_ 1024
#define B_ 8
#define D_ 3

// ---------------- scratch (device globals, POD only) ------------------------
__device__ unsigned short g_adjH [(size_t)D_ * B_ * N_ * N_];       // 48 MB
__device__ unsigned short g_x2   [(size_t)B_ * N_ * F_];
__device__ unsigned short g_sup2 [(size_t)D_ * B_ * 2 * N_ * O_];   // B-split
__device__ unsigned short g_agg2 [(size_t)D_ * B_ * N_ * O_];       // single
__device__ unsigned short g_bigB [(size_t)L_ * 2 * F_ * 896];
__device__ unsigned short g_wih2 [(size_t)L_ * 2 * O_ * 3 * O_];
__device__ float g_cbias[(size_t)L_ * 896];
__device__ float g_gi   [(size_t)D_ * B_ * N_ * 3 * O_];
__device__ float g_ghthw[(size_t)B_ * N_ * 512];
__device__ float g_x    [(size_t)N_ * B_ * O_];

// ---------------- fp16 helpers ----------------------------------------------
__device__ __forceinline__ void hsplit2(float a, float b, uint32_t& hi, uint32_t& lo) {
    __half2 h2 = __floats2half2_rn(a, b);
    hi = *reinterpret_cast<const uint32_t*>(&h2);
    __half2 l2 = __floats2half2_rn(a - __low2float(h2), b - __high2float(h2));
    lo = *reinterpret_cast<const uint32_t*>(&l2);
}
__device__ __forceinline__ uint32_t hpack2(float a, float b) {
    __half2 h2 = __floats2half2_rn(a, b);
    return *reinterpret_cast<const uint32_t*>(&h2);
}
__device__ __forceinline__ void hsplit1(float v, unsigned short& hi, unsigned short& lo) {
    __half h = __float2half_rn(v);
    __half l = __float2half_rn(v - __half2float(h));
    hi = *reinterpret_cast<const unsigned short*>(&h);
    lo = *reinterpret_cast<const unsigned short*>(&l);
}

// cvtA: fp32 (strided) [z][M][K] -> fp16 single out[z][M][K]
__global__ void cvtA_kernel(const float* __restrict__ in,
                            unsigned short* __restrict__ out,
                            long inBatch, long inRow, int M, int K) {
    long idx = (long)blockIdx.x * blockDim.x + threadIdx.x;
    long total = (long)M * (K / 8);
    if (idx >= total) return;
    int m = (int)(idx / (K / 8));
    int kc = (int)(idx % (K / 8)) * 8;
    const float* src = in + (long)blockIdx.z * inBatch + (long)m * inRow + kc;
    float4 v0 = *(const float4*)(src);
    float4 v1 = *(const float4*)(src + 4);
    uint32_t p0 = hpack2(v0.x, v0.y);
    uint32_t p1 = hpack2(v0.z, v0.w);
    uint32_t p2 = hpack2(v1.x, v1.y);
    uint32_t p3 = hpack2(v1.z, v1.w);
    unsigned short* dst = out + (long)blockIdx.z * M * K + (long)m * K + kc;
    *(uint4*)(dst) = make_uint4(p0, p1, p2, p3);
}

// prep_all: builds bigB [L][2F][896], wih2 [L][2O][3O], cbias [L][896]
__global__ void prep_all_kernel(const float* __restrict__ W,
                                const float* __restrict__ Bc,
                                const float* __restrict__ Wh,
                                const float* __restrict__ Bh,
                                const float* __restrict__ Wih,
                                const float* __restrict__ Whh,
                                const float* __restrict__ bhh,
                                unsigned short* __restrict__ bigB,
                                unsigned short* __restrict__ wih2,
                                float* __restrict__ cbias) {
    const int T1 = L_ * F_ * 896;
    const int T2 = L_ * 3 * O_ * O_;
    const int T3 = L_ * 896;
    int idx = blockIdx.x * blockDim.x + threadIdx.x;
    if (idx < T1) {
        int l = idx / (F_ * 896);
        int r = idx % (F_ * 896);
        int k = r / 896;
        int n = r % 896;
        float v;
        if (n < 384)      v = W[(((long)l * D_ + (n >> 7)) * F_ + k) * O_ + (n & 127)];
        else if (n < 768) v = Whh[((long)l * 384 + (n - 384)) * O_ + k];
        else              v = Wh[((long)l * F_ + k) * O_ + (n - 768)];
        unsigned short h, lo;
        hsplit1(v, h, lo);
        unsigned short* dst = bigB + (long)l * 2 * F_ * 896;
        dst[(long)k * 896 + n] = h;
        dst[(long)(F_ + k) * 896 + n] = lo;
    } else if (idx < T1 + T2) {
        int j = idx - T1;
        int l = j / (3 * O_ * O_);
        int r = j % (3 * O_ * O_);
        int n = r / O_;
        int k = r % O_;
        float v = Wih[j];
        unsigned short h, lo;
        hsplit1(v, h, lo);
        unsigned short* dst = wih2 + (long)l * 2 * O_ * 3 * O_;
        dst[(long)k * (3 * O_) + n] = h;
        dst[(long)(O_ + k) * (3 * O_) + n] = lo;
    } else if (idx < T1 + T2 + T3) {
        int j = idx - T1 - T2;
        int l = j / 896;
        int n = j % 896;
        float bv;
        if (n < 384)      bv = Bc[(l * D_ + (n >> 7)) * O_ + (n & 127)];
        else if (n < 768) bv = bhh[l * 384 + (n - 384)];
        else              bv = Bh[l * 128 + (n - 768)];
        cbias[j] = bv;
    }
}

// ---------------- tensor-core GEMM primitives --------------------------------
__device__ __forceinline__ void ldsm_x4(uint32_t* r, uint32_t addr) {
    asm volatile("ldmatrix.sync.aligned.m8n8.x4.shared.b16 {%0,%1,%2,%3}, [%4];"
                 : "=r"(r[0]), "=r"(r[1]), "=r"(r[2]), "=r"(r[3]) : "r"(addr));
}
__device__ __forceinline__ void ldsm_x2t(uint32_t* r, uint32_t addr) {
    asm volatile("ldmatrix.sync.aligned.m8n8.x2.trans.shared.b16 {%0,%1}, [%2];"
                 : "=r"(r[0]), "=r"(r[1]) : "r"(addr));
}
__device__ __forceinline__ void mma_f16(float* d, const uint32_t* a, const uint32_t* b) {
    asm volatile("mma.sync.aligned.m16n8k16.row.col.f32.f16.f16.f32 "
                 "{%0,%1,%2,%3}, {%4,%5,%6,%7}, {%8,%9}, {%0,%1,%2,%3};"
                 : "+f"(d[0]), "+f"(d[1]), "+f"(d[2]), "+f"(d[3])
                 : "r"(a[0]), "r"(a[1]), "r"(a[2]), "r"(a[3]), "r"(b[0]), "r"(b[1]));
}
__device__ __forceinline__ void cp16(uint32_t smem, const void* gptr) {
    asm volatile("cp.async.cg.shared.global [%0], [%1], 16;" :: "r"(smem), "l"(gptr));
}
__device__ __forceinline__ void cp_commit() { asm volatile("cp.async.commit_group;"); }
__device__ __forceinline__ void cp_wait1()  { asm volatile("cp.async.wait_group 1;"); }

// smem: A stages [0,48K): 6 x 8192; B stages [48K,96K): 6 x 8192. 96KB dynamic.
#define STG 8192u
#define B_REGION 49152u
#define SM_DYN 98304

// C[z][m][n] = sum_{k2<2K} A[m][aOff(k2)] * B2[k2][n] (+ bias[n])
// A: [M][K] single fp16; B2: [2K][N]=[Bh;Bl] fp16. aOff wraps at K.
// Tile 128x128x32, 8 warps (2x4), warp 64x32.
// Pipeline: 6 stages, epochs of 2 tiles, one wait+sync per epoch, issue AFTER
// the barrier (reuse distance 3 epochs => race-free).
// emode: 0 fp32 out; 1 fp16 hi/lo B-layout; 2 fp16 single; 3 combined.
__global__ __launch_bounds__(256, 2)
void gemm_f16_kernel(const unsigned short* __restrict__ A2,
                     const unsigned short* __restrict__ B2,
                     void* __restrict__ Cout, const float* __restrict__ bias,
                     int M, int K, int Ncols,
                     long sAd, long sAb, long sBd, long sBb,
                     long sCb, long sBiasD, int BB, int emode,
                     void* __restrict__ Cout2) {
    extern __shared__ char smem[];
    const int z = blockIdx.z;
    const int d = z / BB;
    const int b = z % BB;
    A2 += (long)d * sAd + (long)b * sAb;
    B2 += (long)d * sBd + (long)b * sBb;

    const int row0 = blockIdx.y * 128;
    const int col0 = blockIdx.x * 128;

    const int tid  = threadIdx.x;
    const int lane = tid & 31;
    const int warp = tid >> 5;
    const int wm = warp >> 2;
    const int wn = warp & 3;

    const int arow0 = tid >> 2, ac = tid & 3;
    const int brow0 = tid >> 4, bc = tid & 15;

    const unsigned short* Ag0 = A2 + (long)(row0 + arow0) * K + ac * 8;
    const unsigned short* Ag1 = A2 + (long)(row0 + arow0 + 64) * K + ac * 8;
    const unsigned short* Bg0 = B2 + (long)brow0 * Ncols + col0 + bc * 8;
    const unsigned short* Bg1 = B2 + (long)(brow0 + 16) * Ncols + col0 + bc * 8;

    const int asIdx0 = arow0 * 4 + (ac ^ ((arow0 >> 1) & 3));
    const int asIdx1 = asIdx0 + 256;
    const int bsIdx0 = brow0 * 16 + (bc ^ (brow0 & 7));
    const int bsIdx1 = bsIdx0 + 256;

    const uint32_t smB = (uint32_t)__cvta_generic_to_shared(smem);

    const uint32_t stA0 = smB + (uint32_t)asIdx0 * 16u;
    const uint32_t stA1 = smB + (uint32_t)asIdx1 * 16u;
    const uint32_t stB0 = smB + B_REGION + (uint32_t)bsIdx0 * 16u;
    const uint32_t stB1 = smB + B_REGION + (uint32_t)bsIdx1 * 16u;

    uint32_t aAddr[2][4], bAddr[2][4];
#pragma unroll
    for (int ks = 0; ks < 2; ks++) {
#pragma unroll
        for (int mi = 0; mi < 4; mi++) {
            int r = wm * 64 + mi * 16 + (lane & 15);
            int c = ks * 2 + (lane >> 4);
            aAddr[ks][mi] = smB + (uint32_t)(r * 4 + (c ^ ((r >> 1) & 3))) * 16u;
        }
#pragma unroll
        for (int ni = 0; ni < 4; ni++) {
            int r = ks * 16 + (lane & 15);
            int c = wn * 4 + ni;
            bAddr[ks][ni] = smB + B_REGION + (uint32_t)(r * 16 + (c ^ (r & 7))) * 16u;
        }
    }

    float acc[4][4][4];
#pragma unroll
    for (int mi = 0; mi < 4; mi++)
#pragma unroll
        for (int ni = 0; ni < 4; ni++)
#pragma unroll
            for (int q = 0; q < 4; q++) acc[mi][ni][q] = 0.f;

    const int nT = (2 * K) >> 5;       // always even (8 or 64)

    auto issue = [&](int kt, int stg) {
        const int k2 = kt << 5;
        const int aOff = k2 - (k2 >= K ? K : 0);
        const uint32_t so = (uint32_t)stg * STG;
        cp16(stA0 + so, Ag0 + aOff);
        cp16(stA1 + so, Ag1 + aOff);
        cp16(stB0 + so, Bg0 + (long)k2 * Ncols);
        cp16(stB1 + so, Bg1 + (long)k2 * Ncols);
    };

    // prologue: epochs 0 and 1 (tiles 0..3) into stages 0..3
    issue(0, 0); issue(1, 1); cp_commit();
    if (nT > 2) { issue(2, 2); issue(3, 3); }
    cp_commit();

    int sIss = 4;   // stage for next tile to issue
    int sCmp = 0;   // stage of first tile of current epoch
    const int nE = nT >> 1;
    for (int e = 0; e < nE; e++) {
        cp_wait1();
        __syncthreads();

        const int t0 = 2 * e;
        if (t0 + 4 < nT) {
            issue(t0 + 4, sIss);
            int s2 = sIss + 1; if (s2 == 6) s2 = 0;
            issue(t0 + 5, s2);
            sIss = s2 + 1; if (sIss == 6) sIss = 0;
        }
        cp_commit();

#pragma unroll
        for (int tt = 0; tt < 2; tt++) {
            int st = sCmp + tt; if (st >= 6) st -= 6;
            const uint32_t bofs = (uint32_t)st * STG;
#pragma unroll
            for (int ks = 0; ks < 2; ks++) {
                uint32_t afr[4][4], bfr[4][2];
#pragma unroll
                for (int mi = 0; mi < 4; mi++) ldsm_x4(afr[mi], aAddr[ks][mi] + bofs);
#pragma unroll
                for (int ni = 0; ni < 4; ni++) ldsm_x2t(bfr[ni], bAddr[ks][ni] + bofs);
#pragma unroll
                for (int mi = 0; mi < 4; mi++)
#pragma unroll
                    for (int ni = 0; ni < 4; ni++)
                        mma_f16(acc[mi][ni], afr[mi], bfr[ni]);
            }
        }
        sCmp += 2; if (sCmp >= 6) sCmp -= 6;
    }

    const float* bp = bias ? (bias + (long)d * sBiasD) : (const float*)0;
    float* Cf = (float*)Cout + (long)z * sCb;
    unsigned short* Cb = (unsigned short*)Cout + (long)z * sCb;

#pragma unroll
    for (int mi = 0; mi < 4; mi++) {
        const int r0 = row0 + wm * 64 + mi * 16 + (lane >> 2);
        const int r1 = r0 + 8;
#pragma unroll
        for (int ni = 0; ni < 4; ni++) {
            const int cc = col0 + wn * 32 + ni * 8 + (lane & 3) * 2;
            float bx = 0.f, by = 0.f;
            if (bp) { bx = bp[cc]; by = bp[cc + 1]; }
            const float v00 = acc[mi][ni][0] + bx;
            const float v01 = acc[mi][ni][1] + by;
            const float v10 = acc[mi][ni][2] + bx;
            const float v11 = acc[mi][ni][3] + by;
            if (emode == 0) {
                float* p0 = Cf + (long)r0 * Ncols + cc;
                float* p1 = Cf + (long)r1 * Ncols + cc;
                p0[0] = v00; p0[1] = v01;
                p1[0] = v10; p1[1] = v11;
            } else if (emode == 1) {
                uint32_t h0, l0, h1, l1;
                hsplit2(v00, v01, h0, l0);
                hsplit2(v10, v11, h1, l1);
                *(uint32_t*)(Cb + (long)r0 * Ncols + cc)       = h0;
                *(uint32_t*)(Cb + (long)(M + r0) * Ncols + cc) = l0;
                *(uint32_t*)(Cb + (long)r1 * Ncols + cc)       = h1;
                *(uint32_t*)(Cb + (long)(M + r1) * Ncols + cc) = l1;
            } else if (emode == 2) {
                *(uint32_t*)(Cb + (long)r0 * Ncols + cc) = hpack2(v00, v01);
                *(uint32_t*)(Cb + (long)r1 * Ncols + cc) = hpack2(v10, v11);
            } else {  // emode 3: combined support (cols<384) + ghthw (cols>=384)
                if (blockIdx.x < 3) {
                    unsigned short* S = (unsigned short*)Cout
                        + (long)(blockIdx.x * B_ + z) * (2L * N_ * O_);
                    const int lc = cc & 127;
                    uint32_t h0, l0, h1, l1;
                    hsplit2(v00, v01, h0, l0);
                    hsplit2(v10, v11, h1, l1);
                    *(uint32_t*)(S + (long)r0 * O_ + lc)        = h0;
                    *(uint32_t*)(S + (long)(N_ + r0) * O_ + lc) = l0;
                    *(uint32_t*)(S + (long)r1 * O_ + lc)        = h1;
                    *(uint32_t*)(S + (long)(N_ + r1) * O_ + lc) = l1;
                } else {
                    float* G = (float*)Cout2 + (long)z * ((long)N_ * 512);
                    const int lc = cc - 384;
                    G[(long)r0 * 512 + lc]     = v00;
                    G[(long)r0 * 512 + lc + 1] = v01;
                    G[(long)r1 * 512 + lc]     = v10;
                    G[(long)r1 * 512 + lc + 1] = v11;
                }
            }
        }
    }
}

// ---------------- fused GRU + d-sum + relu + highway (+ next-layer cvt) -----
__device__ __forceinline__ float sigm(float x) { return 1.f / (1.f + expf(-x)); }

__global__ void gru_combine_kernel(const float* __restrict__ gi,
                                   const float* __restrict__ ghthw,
                                   const float* __restrict__ xsrc,
                                   float* __restrict__ xdst,
                                   unsigned short* __restrict__ x2out) {
    int idx = blockIdx.x * blockDim.x + threadIdx.x;  // (n,b,o)
    if (idx >= N_ * B_ * O_) return;
    const int o = idx & (O_ - 1);
    const int nb = idx / O_;
    const int b = nb & (B_ - 1);
    const int n = nb / B_;

    const float h = xsrc[idx];
    const long gbase512 = ((long)b * N_ + n) * 512;
    const float ghr = ghthw[gbase512 + o];
    const float ghz = ghthw[gbase512 + O_ + o];
    const float ghn = ghthw[gbase512 + 2 * O_ + o];
    const float traw = ghthw[gbase512 + 3 * O_ + o];

    float acc = 0.f;
#pragma unroll
    for (int d = 0; d < D_; d++) {
        const long gbase = (((long)d * B_ + b) * N_ + n) * (3 * O_);
        const float gir = gi[gbase + o];
        const float giz = gi[gbase + O_ + o];
        const float gin = gi[gbase + 2 * O_ + o];
        const float r = sigm(gir + ghr);
        const float zz = sigm(giz + ghz);
        const float nn = tanhf(gin + r * ghn);
        acc += (1.f - zz) * nn + zz * h;
    }
    const float outv = fmaxf(acc, 0.f);
    const float t = fmaxf(traw, 0.f);
    const float val = outv * t + h * (1.f - t);
    xdst[idx] = val;
    if (x2out) {
        __half hv = __float2half_rn(val);
        x2out[((long)b * N_ + n) * F_ + o] = *reinterpret_cast<const unsigned short*>(&hv);
    }
}

// ---------------- launch ----------------------------------------------------
extern "C" void kernel_launch(void* const* d_in, const int* in_sizes, int n_in,
                              void* d_out, int out_size) {
    const float* inputs = (const float*)d_in[0];
    const float* adj    = (const float*)d_in[1];
    const float* W      = (const float*)d_in[2];
    const float* Bc     = (const float*)d_in[3];
    const float* Wh     = (const float*)d_in[4];
    const float* Bh     = (const float*)d_in[5];
    const float* Wih    = (const float*)d_in[6];
    const float* Whh    = (const float*)d_in[7];
    const float* bih    = (const float*)d_in[8];
    const float* bhh    = (const float*)d_in[9];
    float* out = (float*)d_out;

    unsigned short *adjH, *x2, *sup2, *agg2, *bigB, *wih2;
    float *cbias, *gi, *ghthw, *xbuf;
    cudaGetSymbolAddress((void**)&adjH,  g_adjH);
    cudaGetSymbolAddress((void**)&x2,    g_x2);
    cudaGetSymbolAddress((void**)&sup2,  g_sup2);
    cudaGetSymbolAddress((void**)&agg2,  g_agg2);
    cudaGetSymbolAddress((void**)&bigB,  g_bigB);
    cudaGetSymbolAddress((void**)&wih2,  g_wih2);
    cudaGetSymbolAddress((void**)&cbias, g_cbias);
    cudaGetSymbolAddress((void**)&gi,    g_gi);
    cudaGetSymbolAddress((void**)&ghthw, g_ghthw);
    cudaGetSymbolAddress((void**)&xbuf,  g_x);

    cudaFuncSetAttribute(gemm_f16_kernel,
                         cudaFuncAttributeMaxDynamicSharedMemorySize, SM_DYN);

    // ---- one-time conversions (3 launches) ----
    cvtA_kernel<<<dim3((N_ * N_ / 8 + 255) / 256, 1, D_ * B_), 256>>>(
        adj, adjH, (long)N_ * N_, (long)N_, N_, N_);
    cvtA_kernel<<<dim3((N_ * F_ / 8 + 255) / 256, 1, B_), 256>>>(
        inputs, x2, (long)F_, (long)B_ * F_, N_, F_);
    {
        const int total = L_ * F_ * 896 + L_ * 3 * O_ * O_ + L_ * 896;
        prep_all_kernel<<<(total + 255) / 256, 256>>>(
            W, Bc, Wh, Bh, Wih, Whh, bhh, bigB, wih2, cbias);
    }

    for (int l = 0; l < L_; l++) {
        const float* xs = (l == 0) ? inputs : xbuf;
        float* xd = (l == L_ - 1) ? out : xbuf;

        // combined: cols 0..383 -> sup2[d][b] (fp16 hi/lo), cols 384..895 -> ghthw
        gemm_f16_kernel<<<dim3(7, N_ / 128, B_), 256, SM_DYN>>>(
            x2, bigB + (long)l * 2 * F_ * 896, sup2, cbias + (long)l * 896,
            N_, F_, 896,
            0, (long)N_ * F_, 0, 0,
            0, 0, B_, 3, ghthw);

        // agg2[d,b] (fp16 single [N][O]) = adjH[d,b] @ sup2[d,b]
        gemm_f16_kernel<<<dim3(1, N_ / 128, D_ * B_), 256, SM_DYN>>>(
            adjH, sup2, agg2, (const float*)0,
            N_, N_, O_,
            (long)B_ * N_ * N_, (long)N_ * N_,
            (long)B_ * 2 * N_ * O_, (long)2 * N_ * O_,
            (long)N_ * O_, 0, B_, 2, (void*)0);

        // gi[d,b][n][3O] = agg2[d,b] @ Wih[l]^T + bih[l]
        gemm_f16_kernel<<<dim3(3, N_ / 128, D_ * B_), 256, SM_DYN>>>(
            agg2, wih2 + (long)l * 2 * O_ * 3 * O_, gi, bih + (long)l * 3 * O_,
            N_, O_, 3 * O_,
            (long)B_ * N_ * O_, (long)N_ * O_, 0, 0,
            (long)N_ * 3 * O_, 0, B_, 0, (void*)0);

        gru_combine_kernel<<<(N_ * B_ * O_) / 256, 256>>>(
            gi, ghthw, xs, xd, (l < L_ - 1) ? x2 : (unsigned short*)0);
    }
}

// round 12
// speedup vs baseline: 1.4959x; 1.4959x over previous
#include <cuda_runtime.h>
#include <cuda_fp16.h>
#include <math.h>
#include <stdint.h>

#define L_ 2
#define F_ 128
#define O_ 128
#define N_ 1024
#define B_ 8
#define D_ 3

// ---------------- scratch (device globals, POD only) ------------------------
// A-side operands: single fp16. B-side operands: hi/lo fp16 split (2K rows).
__device__ unsigned short g_adjH [(size_t)D_ * B_ * N_ * N_];       // 48 MB
__device__ unsigned short g_x2   [(size_t)B_ * N_ * F_];
__device__ unsigned short g_sup2 [(size_t)D_ * B_ * 2 * N_ * O_];   // B-split
__device__ unsigned short g_agg2 [(size_t)D_ * B_ * N_ * O_];       // single
__device__ unsigned short g_bigB [(size_t)L_ * 2 * F_ * 896];   // [2F][ W d0|d1|d2 | Whh^T | Wh ]
__device__ unsigned short g_wih2 [(size_t)L_ * 2 * O_ * 3 * O_];
__device__ float g_cbias[(size_t)L_ * 896];
__device__ float g_gi   [(size_t)D_ * B_ * N_ * 3 * O_];
__device__ float g_ghthw[(size_t)B_ * N_ * 512];
__device__ float g_x    [(size_t)N_ * B_ * O_];

// ---------------- fp16 helpers ----------------------------------------------
__device__ __forceinline__ void hsplit2(float a, float b, uint32_t& hi, uint32_t& lo) {
    __half2 h2 = __floats2half2_rn(a, b);
    hi = *reinterpret_cast<const uint32_t*>(&h2);
    __half2 l2 = __floats2half2_rn(a - __low2float(h2), b - __high2float(h2));
    lo = *reinterpret_cast<const uint32_t*>(&l2);
}
__device__ __forceinline__ uint32_t hpack2(float a, float b) {
    __half2 h2 = __floats2half2_rn(a, b);
    return *reinterpret_cast<const uint32_t*>(&h2);
}
__device__ __forceinline__ void hsplit1(float v, unsigned short& hi, unsigned short& lo) {
    __half h = __float2half_rn(v);
    __half l = __float2half_rn(v - __half2float(h));
    hi = *reinterpret_cast<const unsigned short*>(&h);
    lo = *reinterpret_cast<const unsigned short*>(&l);
}

// cvtA: fp32 (strided) [z][M][K] -> fp16 single out[z][M][K]
__global__ void cvtA_kernel(const float* __restrict__ in,
                            unsigned short* __restrict__ out,
                            long inBatch, long inRow, int M, int K) {
    long idx = (long)blockIdx.x * blockDim.x + threadIdx.x;
    long total = (long)M * (K / 8);
    if (idx >= total) return;
    int m = (int)(idx / (K / 8));
    int kc = (int)(idx % (K / 8)) * 8;
    const float* src = in + (long)blockIdx.z * inBatch + (long)m * inRow + kc;
    float4 v0 = *(const float4*)(src);
    float4 v1 = *(const float4*)(src + 4);
    uint32_t p0 = hpack2(v0.x, v0.y);
    uint32_t p1 = hpack2(v0.z, v0.w);
    uint32_t p2 = hpack2(v1.x, v1.y);
    uint32_t p3 = hpack2(v1.z, v1.w);
    unsigned short* dst = out + (long)blockIdx.z * M * K + (long)m * K + kc;
    *(uint4*)(dst) = make_uint4(p0, p1, p2, p3);
}

// prep_all: builds bigB [L][2F][896], wih2 [L][2O][3O], cbias [L][896]
__global__ void prep_all_kernel(const float* __restrict__ W,
                                const float* __restrict__ Bc,
                                const float* __restrict__ Wh,
                                const float* __restrict__ Bh,
                                const float* __restrict__ Wih,
                                const float* __restrict__ Whh,
                                const float* __restrict__ bhh,
                                unsigned short* __restrict__ bigB,
                                unsigned short* __restrict__ wih2,
                                float* __restrict__ cbias) {
    const int T1 = L_ * F_ * 896;
    const int T2 = L_ * 3 * O_ * O_;
    const int T3 = L_ * 896;
    int idx = blockIdx.x * blockDim.x + threadIdx.x;
    if (idx < T1) {
        int l = idx / (F_ * 896);
        int r = idx % (F_ * 896);
        int k = r / 896;
        int n = r % 896;
        float v;
        if (n < 384)      v = W[(((long)l * D_ + (n >> 7)) * F_ + k) * O_ + (n & 127)];
        else if (n < 768) v = Whh[((long)l * 384 + (n - 384)) * O_ + k];
        else              v = Wh[((long)l * F_ + k) * O_ + (n - 768)];
        unsigned short h, lo;
        hsplit1(v, h, lo);
        unsigned short* dst = bigB + (long)l * 2 * F_ * 896;
        dst[(long)k * 896 + n] = h;
        dst[(long)(F_ + k) * 896 + n] = lo;
    } else if (idx < T1 + T2) {
        int j = idx - T1;                 // enumerates Wih [L][3O][O]
        int l = j / (3 * O_ * O_);
        int r = j % (3 * O_ * O_);
        int n = r / O_;
        int k = r % O_;
        float v = Wih[j];
        unsigned short h, lo;
        hsplit1(v, h, lo);
        unsigned short* dst = wih2 + (long)l * 2 * O_ * 3 * O_;
        dst[(long)k * (3 * O_) + n] = h;
        dst[(long)(O_ + k) * (3 * O_) + n] = lo;
    } else if (idx < T1 + T2 + T3) {
        int j = idx - T1 - T2;
        int l = j / 896;
        int n = j % 896;
        float bv;
        if (n < 384)      bv = Bc[(l * D_ + (n >> 7)) * O_ + (n & 127)];
        else if (n < 768) bv = bhh[l * 384 + (n - 384)];
        else              bv = Bh[l * 128 + (n - 768)];
        cbias[j] = bv;
    }
}

// ---------------- tensor-core GEMM primitives (R10 proven core) --------------
__device__ __forceinline__ void ldsm_x4(uint32_t* r, uint32_t addr) {
    asm volatile("ldmatrix.sync.aligned.m8n8.x4.shared.b16 {%0,%1,%2,%3}, [%4];"
                 : "=r"(r[0]), "=r"(r[1]), "=r"(r[2]), "=r"(r[3]) : "r"(addr));
}
__device__ __forceinline__ void ldsm_x2t(uint32_t* r, uint32_t addr) {
    asm volatile("ldmatrix.sync.aligned.m8n8.x2.trans.shared.b16 {%0,%1}, [%2];"
                 : "=r"(r[0]), "=r"(r[1]) : "r"(addr));
}
__device__ __forceinline__ void mma_f16(float* d, const uint32_t* a, const uint32_t* b) {
    asm volatile("mma.sync.aligned.m16n8k16.row.col.f32.f16.f16.f32 "
                 "{%0,%1,%2,%3}, {%4,%5,%6,%7}, {%8,%9}, {%0,%1,%2,%3};"
                 : "+f"(d[0]), "+f"(d[1]), "+f"(d[2]), "+f"(d[3])
                 : "r"(a[0]), "r"(a[1]), "r"(a[2]), "r"(a[3]), "r"(b[0]), "r"(b[1]));
}
__device__ __forceinline__ void cp16(uint32_t smem, const void* gptr) {
    asm volatile("cp.async.cg.shared.global [%0], [%1], 16;" :: "r"(smem), "l"(gptr));
}
__device__ __forceinline__ void cp_commit() { asm volatile("cp.async.commit_group;"); }
__device__ __forceinline__ void cp_wait2()  { asm volatile("cp.async.wait_group 2;"); }

// C[z][m][n] = sum_{k2<2K} A[m][aOff(k2)] * B2[k2][n] (+ bias[n])
// A: [M][K] single fp16; B2: [2K][N]=[Bh;Bl] fp16.
// terms: A*Bh (k2<K), A*Bl (k2>=K): aOff = k2 - (k2>=K ? K : 0), bOff = k2.
// Tile 128x128x32, 8 warps (2x4), warp 64x32, cp.async 4-stage pipeline.
// emode: 0 fp32 out; 1 fp16 hi/lo B-layout (lo rows +M); 2 fp16 single
//        [m][Ncols]; 3 combined: blockIdx.x<3 -> sup2 (per-d B-layout),
//        else -> ghthw fp32 [z][1024][512] (Cout2).
__global__ __launch_bounds__(256, 2)
void gemm_f16_kernel(const unsigned short* __restrict__ A2,
                     const unsigned short* __restrict__ B2,
                     void* __restrict__ Cout, const float* __restrict__ bias,
                     int M, int K, int Ncols,
                     long sAd, long sAb, long sBd, long sBb,
                     long sCb, long sBiasD, int BB, int emode,
                     void* __restrict__ Cout2) {
    const int z = blockIdx.z;
    const int d = z / BB;
    const int b = z % BB;
    A2 += (long)d * sAd + (long)b * sAb;
    B2 += (long)d * sBd + (long)b * sBb;

    const int row0 = blockIdx.y * 128;
    const int col0 = blockIdx.x * 128;

    __shared__ uint4 As4[4][512];
    __shared__ uint4 Bs4[4][512];

    const int tid  = threadIdx.x;
    const int lane = tid & 31;
    const int warp = tid >> 5;
    const int wm = warp >> 2;
    const int wn = warp & 3;

    const int arow0 = tid >> 2, ac = tid & 3;
    const int brow0 = tid >> 4, bc = tid & 15;

    const unsigned short* Ag0 = A2 + (long)(row0 + arow0) * K + ac * 8;
    const unsigned short* Ag1 = A2 + (long)(row0 + arow0 + 64) * K + ac * 8;
    const unsigned short* Bg0 = B2 + (long)brow0 * Ncols + col0 + bc * 8;
    const unsigned short* Bg1 = B2 + (long)(brow0 + 16) * Ncols + col0 + bc * 8;

    const int asIdx0 = arow0 * 4 + (ac ^ ((arow0 >> 1) & 3));
    const int asIdx1 = asIdx0 + 256;
    const int bsIdx0 = brow0 * 16 + (bc ^ (brow0 & 7));
    const int bsIdx1 = bsIdx0 + 256;

    const uint32_t asB = (uint32_t)__cvta_generic_to_shared(&As4[0][0]);
    const uint32_t bsB = (uint32_t)__cvta_generic_to_shared(&Bs4[0][0]);

    const uint32_t stA0 = asB + (uint32_t)asIdx0 * 16u;
    const uint32_t stA1 = asB + (uint32_t)asIdx1 * 16u;
    const uint32_t stB0 = bsB + (uint32_t)bsIdx0 * 16u;
    const uint32_t stB1 = bsB + (uint32_t)bsIdx1 * 16u;

    uint32_t aAddr[2][4], bAddr[2][4];
#pragma unroll
    for (int ks = 0; ks < 2; ks++) {
#pragma unroll
        for (int mi = 0; mi < 4; mi++) {
            int r = wm * 64 + mi * 16 + (lane & 15);
            int c = ks * 2 + (lane >> 4);
            aAddr[ks][mi] = asB + (uint32_t)(r * 4 + (c ^ ((r >> 1) & 3))) * 16u;
        }
#pragma unroll
        for (int ni = 0; ni < 4; ni++) {
            int r = ks * 16 + (lane & 15);
            int c = wn * 4 + ni;
            bAddr[ks][ni] = bsB + (uint32_t)(r * 16 + (c ^ (r & 7))) * 16u;
        }
    }

    float acc[4][4][4];
#pragma unroll
    for (int mi = 0; mi < 4; mi++)
#pragma unroll
        for (int ni = 0; ni < 4; ni++)
#pragma unroll
            for (int q = 0; q < 4; q++) acc[mi][ni][q] = 0.f;

    const int nT = (2 * K) >> 5;

    auto issue = [&](int kt, int stg) {
        const int k2 = kt << 5;
        const int aOff = k2 - (k2 >= K ? K : 0);
        const int bOff = k2;
        const uint32_t so = (uint32_t)stg * 8192u;
        cp16(stA0 + so, Ag0 + aOff);
        cp16(stA1 + so, Ag1 + aOff);
        cp16(stB0 + so, Bg0 + (long)bOff * Ncols);
        cp16(stB1 + so, Bg1 + (long)bOff * Ncols);
    };

    issue(0, 0); cp_commit();
    issue(1, 1); cp_commit();

    for (int kt = 0; kt < nT; kt++) {
        if (kt + 2 < nT) issue(kt + 2, (kt + 2) & 3);
        cp_commit();
        cp_wait2();
        __syncthreads();

        const uint32_t bofs = (uint32_t)(kt & 3) * 8192u;
#pragma unroll
        for (int ks = 0; ks < 2; ks++) {
            uint32_t afr[4][4], bfr[4][2];
#pragma unroll
            for (int mi = 0; mi < 4; mi++) ldsm_x4(afr[mi], aAddr[ks][mi] + bofs);
#pragma unroll
            for (int ni = 0; ni < 4; ni++) ldsm_x2t(bfr[ni], bAddr[ks][ni] + bofs);
#pragma unroll
            for (int mi = 0; mi < 4; mi++)
#pragma unroll
                for (int ni = 0; ni < 4; ni++)
                    mma_f16(acc[mi][ni], afr[mi], bfr[ni]);
        }
    }

    const float* bp = bias ? (bias + (long)d * sBiasD) : (const float*)0;
    float* Cf = (float*)Cout + (long)z * sCb;
    unsigned short* Cb = (unsigned short*)Cout + (long)z * sCb;

#pragma unroll
    for (int mi = 0; mi < 4; mi++) {
        const int r0 = row0 + wm * 64 + mi * 16 + (lane >> 2);
        const int r1 = r0 + 8;
#pragma unroll
        for (int ni = 0; ni < 4; ni++) {
            const int cc = col0 + wn * 32 + ni * 8 + (lane & 3) * 2;
            float bx = 0.f, by = 0.f;
            if (bp) { bx = bp[cc]; by = bp[cc + 1]; }
            const float v00 = acc[mi][ni][0] + bx;
            const float v01 = acc[mi][ni][1] + by;
            const float v10 = acc[mi][ni][2] + bx;
            const float v11 = acc[mi][ni][3] + by;
            if (emode == 0) {
                float* p0 = Cf + (long)r0 * Ncols + cc;
                float* p1 = Cf + (long)r1 * Ncols + cc;
                p0[0] = v00; p0[1] = v01;
                p1[0] = v10; p1[1] = v11;
            } else if (emode == 1) {
                uint32_t h0, l0, h1, l1;
                hsplit2(v00, v01, h0, l0);
                hsplit2(v10, v11, h1, l1);
                *(uint32_t*)(Cb + (long)r0 * Ncols + cc)       = h0;
                *(uint32_t*)(Cb + (long)(M + r0) * Ncols + cc) = l0;
                *(uint32_t*)(Cb + (long)r1 * Ncols + cc)       = h1;
                *(uint32_t*)(Cb + (long)(M + r1) * Ncols + cc) = l1;
            } else if (emode == 2) {
                // single fp16 out [m][Ncols]
                *(uint32_t*)(Cb + (long)r0 * Ncols + cc) = hpack2(v00, v01);
                *(uint32_t*)(Cb + (long)r1 * Ncols + cc) = hpack2(v10, v11);
            } else {  // emode 3: combined support (cols<384) + ghthw (cols>=384)
                if (blockIdx.x < 3) {
                    // sup2[d=bx][b=z]: [2*1024][128], hi rows [0,1024), lo [1024,2048)
                    unsigned short* S = (unsigned short*)Cout
                        + (long)(blockIdx.x * B_ + z) * (2L * N_ * O_);
                    const int lc = cc & 127;
                    uint32_t h0, l0, h1, l1;
                    hsplit2(v00, v01, h0, l0);
                    hsplit2(v10, v11, h1, l1);
                    *(uint32_t*)(S + (long)r0 * O_ + lc)        = h0;
                    *(uint32_t*)(S + (long)(N_ + r0) * O_ + lc) = l0;
                    *(uint32_t*)(S + (long)r1 * O_ + lc)        = h1;
                    *(uint32_t*)(S + (long)(N_ + r1) * O_ + lc) = l1;
                } else {
                    float* G = (float*)Cout2 + (long)z * ((long)N_ * 512);
                    const int lc = cc - 384;
                    G[(long)r0 * 512 + lc]     = v00;
                    G[(long)r0 * 512 + lc + 1] = v01;
                    G[(long)r1 * 512 + lc]     = v10;
                    G[(long)r1 * 512 + lc + 1] = v11;
                }
            }
        }
    }
}

// ---------------- fused GRU + d-sum + relu + highway (+ next-layer cvt) -----
__device__ __forceinline__ float sigm(float x) { return 1.f / (1.f + expf(-x)); }

__global__ void gru_combine_kernel(const float* __restrict__ gi,
                                   const float* __restrict__ ghthw,
                                   const float* __restrict__ xsrc,
                                   float* __restrict__ xdst,
                                   unsigned short* __restrict__ x2out) {
    int idx = blockIdx.x * blockDim.x + threadIdx.x;  // (n,b,o)
    if (idx >= N_ * B_ * O_) return;
    const int o = idx & (O_ - 1);
    const int nb = idx / O_;
    const int b = nb & (B_ - 1);
    const int n = nb / B_;

    const float h = xsrc[idx];
    const long gbase512 = ((long)b * N_ + n) * 512;
    const float ghr = ghthw[gbase512 + o];
    const float ghz = ghthw[gbase512 + O_ + o];
    const float ghn = ghthw[gbase512 + 2 * O_ + o];
    const float traw = ghthw[gbase512 + 3 * O_ + o];

    float acc = 0.f;
#pragma unroll
    for (int d = 0; d < D_; d++) {
        const long gbase = (((long)d * B_ + b) * N_ + n) * (3 * O_);
        const float gir = gi[gbase + o];
        const float giz = gi[gbase + O_ + o];
        const float gin = gi[gbase + 2 * O_ + o];
        const float r = sigm(gir + ghr);
        const float zz = sigm(giz + ghz);
        const float nn = tanhf(gin + r * ghn);
        acc += (1.f - zz) * nn + zz * h;
    }
    const float outv = fmaxf(acc, 0.f);
    const float t = fmaxf(traw, 0.f);
    const float val = outv * t + h * (1.f - t);
    xdst[idx] = val;
    if (x2out) {
        __half hv = __float2half_rn(val);
        x2out[((long)b * N_ + n) * F_ + o] = *reinterpret_cast<const unsigned short*>(&hv);
    }
}

// ---------------- launch ----------------------------------------------------
extern "C" void kernel_launch(void* const* d_in, const int* in_sizes, int n_in,
                              void* d_out, int out_size) {
    const float* inputs = (const float*)d_in[0];
    const float* adj    = (const float*)d_in[1];
    const float* W      = (const float*)d_in[2];
    const float* Bc     = (const float*)d_in[3];
    const float* Wh     = (const float*)d_in[4];
    const float* Bh     = (const float*)d_in[5];
    const float* Wih    = (const float*)d_in[6];
    const float* Whh    = (const float*)d_in[7];
    const float* bih    = (const float*)d_in[8];
    const float* bhh    = (const float*)d_in[9];
    float* out = (float*)d_out;

    unsigned short *adjH, *x2, *sup2, *agg2, *bigB, *wih2;
    float *cbias, *gi, *ghthw, *xbuf;
    cudaGetSymbolAddress((void**)&adjH,  g_adjH);
    cudaGetSymbolAddress((void**)&x2,    g_x2);
    cudaGetSymbolAddress((void**)&sup2,  g_sup2);
    cudaGetSymbolAddress((void**)&agg2,  g_agg2);
    cudaGetSymbolAddress((void**)&bigB,  g_bigB);
    cudaGetSymbolAddress((void**)&wih2,  g_wih2);
    cudaGetSymbolAddress((void**)&cbias, g_cbias);
    cudaGetSymbolAddress((void**)&gi,    g_gi);
    cudaGetSymbolAddress((void**)&ghthw, g_ghthw);
    cudaGetSymbolAddress((void**)&xbuf,  g_x);

    // ---- one-time conversions (3 launches) ----
    cvtA_kernel<<<dim3((N_ * N_ / 8 + 255) / 256, 1, D_ * B_), 256>>>(
        adj, adjH, (long)N_ * N_, (long)N_, N_, N_);
    cvtA_kernel<<<dim3((N_ * F_ / 8 + 255) / 256, 1, B_), 256>>>(
        inputs, x2, (long)F_, (long)B_ * F_, N_, F_);
    {
        const int total = L_ * F_ * 896 + L_ * 3 * O_ * O_ + L_ * 896;
        prep_all_kernel<<<(total + 255) / 256, 256>>>(
            W, Bc, Wh, Bh, Wih, Whh, bhh, bigB, wih2, cbias);
    }

    for (int l = 0; l < L_; l++) {
        const float* xs = (l == 0) ? inputs : xbuf;
        float* xd = (l == L_ - 1) ? out : xbuf;

        // combined: cols 0..383 -> sup2[d][b] (fp16 hi/lo), cols 384..895 -> ghthw
        gemm_f16_kernel<<<dim3(7, N_ / 128, B_), 256>>>(
            x2, bigB + (long)l * 2 * F_ * 896, sup2, cbias + (long)l * 896,
            N_, F_, 896,
            0, (long)N_ * F_, 0, 0,
            0, 0, B_, 3, ghthw);

        // agg2[d,b] (fp16 single [N][O]) = adjH[d,b] @ sup2[d,b]
        gemm_f16_kernel<<<dim3(1, N_ / 128, D_ * B_), 256>>>(
            adjH, sup2, agg2, (const float*)0,
            N_, N_, O_,
            (long)B_ * N_ * N_, (long)N_ * N_,
            (long)B_ * 2 * N_ * O_, (long)2 * N_ * O_,
            (long)N_ * O_, 0, B_, 2, (void*)0);

        // gi[d,b][n][3O] = agg2[d,b] @ Wih[l]^T + bih[l]
        gemm_f16_kernel<<<dim3(3, N_ / 128, D_ * B_), 256>>>(
            agg2, wih2 + (long)l * 2 * O_ * 3 * O_, gi, bih + (long)l * 3 * O_,
            N_, O_, 3 * O_,
            (long)B_ * N_ * O_, (long)N_ * O_, 0, 0,
            (long)N_ * 3 * O_, 0, B_, 0, (void*)0);

        gru_combine_kernel<<<(N_ * B_ * O_) / 256, 256>>>(
            gi, ghthw, xs, xd, (l < L_ - 1) ? x2 : (unsigned short*)0);
    }
}